// round 15
// baseline (speedup 1.0000x reference)
#include <cuda_runtime.h>
#include <cuda_fp16.h>
#include <cstdint>

// ---------------------------------------------------------------------------
// BenesBlock via mma.sync (HMMA), single-pass fp16 GEMMs.
// R14: 128x128 CTA tile covered by 4 warps of 64x64 (2x2) -> operand smem
// duplication (A x2, B x2) instead of (x2, x4): per-MAC smem traffic -25%.
// 128-thread CTAs, acc 128 regs/thread, launch_bounds(128,2) -> 2 CTAs/SM.
// Residual exact fp32; h fp16 raw; LN+lrelu fused into gemm2's A fragments.
// ---------------------------------------------------------------------------

#define L    8192
#define NU   512
#define M_   4096
#define K1   1024
#define N1   2048
#define K2   2048
#define N2   1024
#define CW_F 0.10897247358851683f
#define EPS_F 1e-6f

#define STAGE 32768                       // A16K | B16K
#define SMEM_DYN (2 * STAGE + 8192)       // + LN coeff cache = 72KB -> 2 CTAs/SM

// ---------------------------------------------------------------------------
__device__ __align__(16) float  g_y32[2][L * NU];         // exact residual
__device__ __align__(16) __half g_y16[2][L * NU];         // GEMM1 A operand
__device__ __align__(16) __half g_h2[M_ * N1];            // raw h (fp16)
__device__ __align__(16) __half g_w1t[3][N1 * K1];        // [stage][N,K] fp16
__device__ __align__(16) __half g_w2t[3][N2 * K2];
__device__ __align__(16) float g_part[32][2 * N1];
__device__ __align__(16) __half g_lns[N1];                // rstd (fp16)
__device__ __align__(16) __half g_lnb[N1];                // -mean*rstd (fp16)
__device__ float g_sig[3 * NU];

// ---------------------------------------------------------------------------
__device__ __forceinline__ uint32_t smem_u32(const void* p) {
    uint32_t a;
    asm("{ .reg .u64 t; cvta.to.shared.u64 t, %1; cvt.u32.u64 %0, t; }" : "=r"(a) : "l"(p));
    return a;
}
__device__ __forceinline__ uint32_t sw128(uint32_t off) { return off ^ ((off >> 3) & 0x70); }

#define CP16(s, g) asm volatile("cp.async.cg.shared.global [%0], [%1], 16;" :: "r"(s), "l"(g))
#define CP_COMMIT() asm volatile("cp.async.commit_group;" ::: "memory")

#define LDSM4(r0, r1, r2, r3, addr)                                              \
    asm volatile("ldmatrix.sync.aligned.m8n8.x4.shared.b16 {%0,%1,%2,%3}, [%4];" \
                 : "=r"(r0), "=r"(r1), "=r"(r2), "=r"(r3) : "r"(addr))

#define MMA(acc, a, b0, b1)                                                      \
    asm volatile("mma.sync.aligned.m16n8k16.row.col.f32.f16.f16.f32 "            \
                 "{%0,%1,%2,%3}, {%4,%5,%6,%7}, {%8,%9}, {%0,%1,%2,%3};"         \
                 : "+f"((acc)[0]), "+f"((acc)[1]), "+f"((acc)[2]), "+f"((acc)[3])\
                 : "r"((a)[0]), "r"((a)[1]), "r"((a)[2]), "r"((a)[3]),           \
                   "r"(b0), "r"(b1))

// ---------------------------------------------------------------------------
__global__ void copy_x_kernel(const float* __restrict__ x,
                              const float* __restrict__ rs_f,
                              const float* __restrict__ rs_r,
                              const float* __restrict__ rs_m) {
    if (blockIdx.x == (L * NU) / 256) {
        for (int i = threadIdx.x; i < 3 * NU; i += 256) {
            const float* src = (i < NU) ? rs_f : (i < 2 * NU) ? rs_r : rs_m;
            float v = src[i & (NU - 1)];
            g_sig[i] = 1.0f / (1.0f + expf(-v));
        }
        return;
    }
    int i = blockIdx.x * 256 + threadIdx.x;
    float v = x[i];
    g_y32[0][i] = v;
    g_y16[0][i] = __float2half_rn(v);
}

// All 6 weight transposes in one launch. z: stage = z>>1, which = z&1.
__global__ void transpose_half_all(const float* __restrict__ w1f, const float* __restrict__ w2f,
                                   const float* __restrict__ w1r, const float* __restrict__ w2r,
                                   const float* __restrict__ w1m, const float* __restrict__ w2m) {
    __shared__ float t[32][33];
    int stage = blockIdx.z >> 1;
    int which = blockIdx.z & 1;
    int R = which ? K2 : K1;
    int C = which ? N2 : N1;
    if ((int)blockIdx.x * 32 >= C || (int)blockIdx.y * 32 >= R) return;
    const float* w = which ? (stage == 0 ? w2f : stage == 1 ? w2r : w2m)
                           : (stage == 0 ? w1f : stage == 1 ? w1r : w1m);
    __half* o = which ? g_w2t[stage] : g_w1t[stage];
    int c0 = blockIdx.x * 32, r0 = blockIdx.y * 32;
    for (int j = threadIdx.y; j < 32; j += 8)
        t[j][threadIdx.x] = w[(size_t)(r0 + j) * C + c0 + threadIdx.x];
    __syncthreads();
    for (int j = threadIdx.y; j < 32; j += 8) {
        float v = t[threadIdx.x][j];
        o[(size_t)(c0 + j) * R + r0 + threadIdx.x] = __float2half_rn(v);
    }
}

// ---------------------------------------------------------------------------
// Reduce partials -> fp16 LN coefficients.
__global__ void stats_final_kernel() {     // grid 8, block 256
    int c = blockIdx.x * 256 + threadIdx.x;
    float s = 0.f, q = 0.f;
#pragma unroll
    for (int rg = 0; rg < 32; rg++) { s += g_part[rg][2 * c]; q += g_part[rg][2 * c + 1]; }
    float mean = s * (1.0f / M_);
    float var = q * (1.0f / M_) - mean * mean;
    float rstd = rsqrtf(var + EPS_F);
    g_lns[c] = __float2half_rn(rstd);
    g_lnb[c] = __float2half_rn(-mean * rstd);
}

// ---------------------------------------------------------------------------
// Stage loader: 128 threads; each thread copies one full 128B row of A and B.
__device__ __forceinline__ void load_stage(uint32_t sb, int s, int ck,
                                           const __half* A, const __half* B,
                                           int Kt, int m0, int n0) {
    int r = threadIdx.x;                   // 0..127
    uint32_t base = sb + s * STAGE;
    size_t rs = (size_t)Kt * 2;
    size_t kb = (size_t)ck * 128;
    const char* pA = (const char*)A + (size_t)(m0 + r) * rs + kb;
    const char* pB = (const char*)B + (size_t)(n0 + r) * rs + kb;
#pragma unroll
    for (int ch = 0; ch < 8; ch++) {
        uint32_t so = sw128((uint32_t)(r * 128 + ch * 16));
        CP16(base + so,         pA + ch * 16);
        CP16(base + 16384 + so, pB + ch * 16);
    }
    CP_COMMIT();
}

// 64x64 warp tile: wm = wid&1, wn = wid>>1 (2x2 over 128x128).
__device__ __forceinline__ void compute_chunk(uint32_t base, int lane, int wm, int wn,
                                              float acc[4][8][4]) {
#pragma unroll
    for (int k16 = 0; k16 < 4; k16++) {
        uint32_t koff = k16 * 32 + (lane >> 4) * 16;
        uint32_t ah[4][4];
#pragma unroll
        for (int mt = 0; mt < 4; mt++) {
            int row = wm * 64 + mt * 16 + (lane & 15);
            LDSM4(ah[mt][0], ah[mt][1], ah[mt][2], ah[mt][3],
                  base + sw128((uint32_t)(row * 128) + koff));
        }
        uint32_t bh[8][2];
#pragma unroll
        for (int g = 0; g < 4; g++) {
            int row = wn * 64 + g * 16 + (lane & 15);
            uint32_t q0, q1, q2, q3;
            LDSM4(q0, q1, q2, q3, base + 16384 + sw128((uint32_t)(row * 128) + koff));
            bh[2 * g][0] = q0; bh[2 * g][1] = q2;
            bh[2 * g + 1][0] = q1; bh[2 * g + 1][1] = q3;
        }
#pragma unroll
        for (int mt = 0; mt < 4; mt++)
#pragma unroll
            for (int nt = 0; nt < 8; nt++)
                MMA(acc[mt][nt], ah[mt], bh[nt][0], bh[nt][1]);
    }
}

// gemm2 chunk: LN+lrelu applied to A fragments (k-mapping validated in R11).
__device__ __forceinline__ void compute_chunk_ln(uint32_t base, int lane, int wm, int wn,
                                                 float acc[4][8][4],
                                                 const __half2* s2, const __half2* b2) {
    const __half2 c02 = __float2half2_rn(0.2f);
#pragma unroll
    for (int k16 = 0; k16 < 4; k16++) {
        uint32_t koff = k16 * 32 + (lane >> 4) * 16;
        int si = k16 * 8 + (lane & 3);
        __half2 sA = s2[si], bA = b2[si];
        __half2 sB = s2[si + 4], bB = b2[si + 4];
        uint32_t ah[4][4];
#pragma unroll
        for (int mt = 0; mt < 4; mt++) {
            int row = wm * 64 + mt * 16 + (lane & 15);
            LDSM4(ah[mt][0], ah[mt][1], ah[mt][2], ah[mt][3],
                  base + sw128((uint32_t)(row * 128) + koff));
#pragma unroll
            for (int j = 0; j < 4; j++) {
                __half2 h = *(__half2*)&ah[mt][j];
                __half2 t = __hfma2(h, (j < 2) ? sA : sB, (j < 2) ? bA : bB);
                t = __hmax2(t, __hmul2(t, c02));
                ah[mt][j] = *(uint32_t*)&t;
            }
        }
        uint32_t bh[8][2];
#pragma unroll
        for (int g = 0; g < 4; g++) {
            int row = wn * 64 + g * 16 + (lane & 15);
            uint32_t q0, q1, q2, q3;
            LDSM4(q0, q1, q2, q3, base + 16384 + sw128((uint32_t)(row * 128) + koff));
            bh[2 * g][0] = q0; bh[2 * g][1] = q2;
            bh[2 * g + 1][0] = q1; bh[2 * g + 1][1] = q3;
        }
#pragma unroll
        for (int mt = 0; mt < 4; mt++)
#pragma unroll
            for (int nt = 0; nt < 8; nt++)
                MMA(acc[mt][nt], ah[mt], bh[nt][0], bh[nt][1]);
    }
}

// ---------------------------------------------------------------------------
// GEMM1: h(fp16 raw) = y16 @ w1t^T + fused per-CTA stats partials.
__global__ __launch_bounds__(128, 2) void gemm1_mma(int cur, int stage) {
    extern __shared__ char smem[];
    uint32_t sb = smem_u32(smem);
    int m0 = blockIdx.y * 128, n0 = blockIdx.x * 128;
    float acc[4][8][4];
#pragma unroll
    for (int i = 0; i < 4; i++)
#pragma unroll
        for (int j = 0; j < 8; j++)
#pragma unroll
            for (int q = 0; q < 4; q++) acc[i][j][q] = 0.f;

    const int lane = threadIdx.x & 31, wid = threadIdx.x >> 5;
    const int wm = wid & 1, wn = wid >> 1;
    const __half* A = g_y16[cur];
    const __half* B = g_w1t[stage];
    const int NK = K1 >> 6;

    load_stage(sb, 0, 0, A, B, K1, m0, n0);
    for (int ck = 0; ck < NK; ck++) {
        if (ck + 1 < NK) {
            load_stage(sb, (ck + 1) & 1, ck + 1, A, B, K1, m0, n0);
            asm volatile("cp.async.wait_group 1;" ::: "memory");
        } else {
            asm volatile("cp.async.wait_group 0;" ::: "memory");
        }
        __syncthreads();
        compute_chunk(sb + (ck & 1) * STAGE, lane, wm, wn, acc);
        __syncthreads();
    }

#pragma unroll
    for (int mt = 0; mt < 4; mt++) {
        int r0 = m0 + wm * 64 + mt * 16 + (lane >> 2);
#pragma unroll
        for (int nt = 0; nt < 8; nt++) {
            int cc = n0 + wn * 64 + nt * 8 + (lane & 3) * 2;
            *(__half2*)&g_h2[(size_t)r0 * N1 + cc] =
                __floats2half2_rn(acc[mt][nt][0], acc[mt][nt][1]);
            *(__half2*)&g_h2[(size_t)(r0 + 8) * N1 + cc] =
                __floats2half2_rn(acc[mt][nt][2], acc[mt][nt][3]);
        }
    }

    // per-CTA column stats over this CTA's 128 rows (exact fp32 acc)
    float s[8][2], q[8][2];
#pragma unroll
    for (int nt = 0; nt < 8; nt++)
#pragma unroll
        for (int p = 0; p < 2; p++) {
            float sv = 0.f, qv = 0.f;
#pragma unroll
            for (int mt = 0; mt < 4; mt++) {
                float a0 = acc[mt][nt][p], a1 = acc[mt][nt][2 + p];
                sv += a0 + a1;
                qv += a0 * a0 + a1 * a1;
            }
            s[nt][p] = sv;
            q[nt][p] = qv;
        }
#pragma unroll
    for (int off = 4; off < 32; off <<= 1)
#pragma unroll
        for (int nt = 0; nt < 8; nt++)
#pragma unroll
            for (int p = 0; p < 2; p++) {
                s[nt][p] += __shfl_xor_sync(0xffffffffu, s[nt][p], off);
                q[nt][p] += __shfl_xor_sync(0xffffffffu, q[nt][p], off);
            }
    float* red = (float*)smem;             // [2 wm][128 col][2] = 2KB scratch
    if (lane < 4) {
#pragma unroll
        for (int nt = 0; nt < 8; nt++)
#pragma unroll
            for (int p = 0; p < 2; p++) {
                int cl = wn * 64 + nt * 8 + lane * 2 + p;
                red[(wm * 128 + cl) * 2 + 0] = s[nt][p];
                red[(wm * 128 + cl) * 2 + 1] = q[nt][p];
            }
    }
    __syncthreads();
    {
        int cl = threadIdx.x;              // 0..127
        float S = red[cl * 2]     + red[(128 + cl) * 2];
        float Q = red[cl * 2 + 1] + red[(128 + cl) * 2 + 1];
        g_part[blockIdx.y][2 * (n0 + cl)]     = S;
        g_part[blockIdx.y][2 * (n0 + cl) + 1] = Q;
    }
}

// ---------------------------------------------------------------------------
// GEMM2: cand = lrelu(LN(h)) @ w2t^T (LN fused post-ldmatrix);
// epilogue: +b2, fp32 residual, Benes scatter.
__global__ __launch_bounds__(128, 2) void gemm2_mma(int stage, int dir, int cur,
                                                    const float* __restrict__ b2,
                                                    float* __restrict__ dext) {
    extern __shared__ char smem[];
    uint32_t sb = smem_u32(smem);
    int m0 = blockIdx.y * 128, n0 = blockIdx.x * 128;

    // preload LN coeff cache (4KB + 4KB) with 128 threads (2 uint4 each)
    __half* lns_c = (__half*)(smem + 2 * STAGE);
    __half* lnb_c = (__half*)(smem + 2 * STAGE + 4096);
#pragma unroll
    for (int i = 0; i < 2; i++) {
        ((uint4*)lns_c)[threadIdx.x + i * 128] = ((const uint4*)g_lns)[threadIdx.x + i * 128];
        ((uint4*)lnb_c)[threadIdx.x + i * 128] = ((const uint4*)g_lnb)[threadIdx.x + i * 128];
    }
    __syncthreads();

    float acc[4][8][4];
#pragma unroll
    for (int i = 0; i < 4; i++)
#pragma unroll
        for (int j = 0; j < 8; j++)
#pragma unroll
            for (int q = 0; q < 4; q++) acc[i][j][q] = 0.f;

    const int lane = threadIdx.x & 31, wid = threadIdx.x >> 5;
    const int wm = wid & 1, wn = wid >> 1;
    const __half* A = g_h2;
    const __half* B = g_w2t[stage];
    const int NK = K2 >> 6;

    load_stage(sb, 0, 0, A, B, K2, m0, n0);
    for (int ck = 0; ck < NK; ck++) {
        if (ck + 1 < NK) {
            load_stage(sb, (ck + 1) & 1, ck + 1, A, B, K2, m0, n0);
            asm volatile("cp.async.wait_group 1;" ::: "memory");
        } else {
            asm volatile("cp.async.wait_group 0;" ::: "memory");
        }
        __syncthreads();
        compute_chunk_ln(sb + (ck & 1) * STAGE, lane, wm, wn, acc,
                         (const __half2*)lns_c + ck * 32,
                         (const __half2*)lnb_c + ck * 32);
        __syncthreads();
    }

    const float* y = g_y32[cur];
    float* oy = g_y32[cur ^ 1];
    __half* o16 = g_y16[cur ^ 1];

#pragma unroll
    for (int mt = 0; mt < 4; mt++) {
        int rbase = m0 + wm * 64 + mt * 16 + (lane >> 2);
#pragma unroll
        for (int nt = 0; nt < 8; nt++) {
            int n = n0 + wn * 64 + nt * 8 + (lane & 3) * 2;
            int c = n & (NU - 1);
            int b = n >> 9;
            float2 bias = *(const float2*)&b2[n];
            float sig0 = g_sig[stage * NU + c];
            float sig1 = g_sig[stage * NU + c + 1];
#pragma unroll
            for (int hf = 0; hf < 2; hf++) {
                int r = rbase + hf * 8;
                int rowY = 2 * r + b;
                float cand0 = acc[mt][nt][hf * 2 + 0] + bias.x;
                float cand1 = acc[mt][nt][hf * 2 + 1] + bias.y;
                float2 yv = *(const float2*)&y[(size_t)rowY * NU + c];
                float v0 = sig0 * yv.x + cand0 * CW_F;
                float v1 = sig1 * yv.y + cand1 * CW_F;
                int dst;
                if (dir == 0)      dst = (rowY < M_) ? (2 * rowY) : (2 * rowY - L + 1);
                else if (dir == 1) dst = (rowY & 1) ? (M_ + (rowY >> 1)) : (rowY >> 1);
                else               dst = rowY;
                if (dext) {
                    *(float2*)&dext[(size_t)dst * NU + c] = make_float2(v0, v1);
                } else {
                    *(float2*)&oy[(size_t)dst * NU + c] = make_float2(v0, v1);
                    *(__half2*)&o16[(size_t)dst * NU + c] =
                        __halves2half2(__float2half_rn(v0), __float2half_rn(v1));
                }
            }
        }
    }
}

// ---------------------------------------------------------------------------
extern "C" void kernel_launch(void* const* d_in, const int* in_sizes, int n_in,
                              void* d_out, int out_size) {
    const float* x = (const float*)d_in[0];
    const float* rs[3] = {(const float*)d_in[1], (const float*)d_in[5], (const float*)d_in[9]};
    const float* w1[3] = {(const float*)d_in[2], (const float*)d_in[6], (const float*)d_in[10]};
    const float* w2[3] = {(const float*)d_in[3], (const float*)d_in[7], (const float*)d_in[11]};
    const float* b2[3] = {(const float*)d_in[4], (const float*)d_in[8], (const float*)d_in[12]};
    float* out = (float*)d_out;

    cudaFuncSetAttribute(gemm1_mma, cudaFuncAttributeMaxDynamicSharedMemorySize, SMEM_DYN);
    cudaFuncSetAttribute(gemm2_mma, cudaFuncAttributeMaxDynamicSharedMemorySize, SMEM_DYN);

    copy_x_kernel<<<(L * NU) / 256 + 1, 256>>>(x, rs[0], rs[1], rs[2]);
    transpose_half_all<<<dim3(64, 64, 6), dim3(32, 8)>>>(w1[0], w2[0], w1[1], w2[1], w1[2], w2[2]);

    dim3 g1(N1 / 128, M_ / 128);   // (16, 32)
    dim3 g2(N2 / 128, M_ / 128);   // (8, 32)

    int cur = 0;
    for (int step = 0; step < 25; step++) {
        int stage = (step < 12) ? 0 : (step < 24) ? 1 : 2;
        int dir = stage;
        gemm1_mma<<<g1, 128, SMEM_DYN>>>(cur, stage);
        stats_final_kernel<<<8, 256>>>();
        gemm2_mma<<<g2, 128, SMEM_DYN>>>(stage, dir, cur, b2[stage],
                                         (step == 24) ? out : nullptr);
        cur ^= 1;
    }
}

// round 16
// speedup vs baseline: 1.3914x; 1.3914x over previous
#include <cuda_runtime.h>
#include <cuda_fp16.h>
#include <cstdint>

// ---------------------------------------------------------------------------
// BenesBlock via mma.sync (HMMA), single-pass fp16 GEMMs.
// R15 = R7 champion GEMM core (256 thr, 8 warps 32x64, 2-stage, 2 barriers)
// with fp16 h end-to-end: gemm1 writes raw fp16 h, prep2 (fp16 in/out) does
// LN+lrelu, gemm2 is the pure R7 GEMM. 4 launches/step.
// ---------------------------------------------------------------------------

#define L    8192
#define NU   512
#define M_   4096
#define K1   1024
#define N1   2048
#define K2   2048
#define N2   1024
#define CW_F 0.10897247358851683f
#define EPS_F 1e-6f

#define STAGE 32768                 // A16K | B16K
#define SMEM_DYN (2 * STAGE)        // 64KB double buffered -> 2 CTAs/SM

// ---------------------------------------------------------------------------
__device__ __align__(16) float  g_y32[2][L * NU];         // exact residual
__device__ __align__(16) __half g_y16[2][L * NU];         // GEMM1 A operand
__device__ __align__(16) __half g_hraw[M_ * N1];          // raw h (fp16)
__device__ __align__(16) __half g_h2[M_ * N1];            // LN'd h (fp16)
__device__ __align__(16) __half g_w1t[3][N1 * K1];        // [stage][N,K] fp16
__device__ __align__(16) __half g_w2t[3][N2 * K2];
__device__ __align__(16) float g_part[32][2 * N1];
__device__ __align__(16) float g_stats[2 * N1];           // (mean, rstd)
__device__ float g_sig[3 * NU];

// ---------------------------------------------------------------------------
__device__ __forceinline__ uint32_t smem_u32(const void* p) {
    uint32_t a;
    asm("{ .reg .u64 t; cvta.to.shared.u64 t, %1; cvt.u32.u64 %0, t; }" : "=r"(a) : "l"(p));
    return a;
}
__device__ __forceinline__ uint32_t sw128(uint32_t off) { return off ^ ((off >> 3) & 0x70); }

#define CP16(s, g) asm volatile("cp.async.cg.shared.global [%0], [%1], 16;" :: "r"(s), "l"(g))
#define CP_COMMIT() asm volatile("cp.async.commit_group;" ::: "memory")

#define LDSM4(r0, r1, r2, r3, addr)                                              \
    asm volatile("ldmatrix.sync.aligned.m8n8.x4.shared.b16 {%0,%1,%2,%3}, [%4];" \
                 : "=r"(r0), "=r"(r1), "=r"(r2), "=r"(r3) : "r"(addr))

#define MMA(acc, a, b0, b1)                                                      \
    asm volatile("mma.sync.aligned.m16n8k16.row.col.f32.f16.f16.f32 "            \
                 "{%0,%1,%2,%3}, {%4,%5,%6,%7}, {%8,%9}, {%0,%1,%2,%3};"         \
                 : "+f"((acc)[0]), "+f"((acc)[1]), "+f"((acc)[2]), "+f"((acc)[3])\
                 : "r"((a)[0]), "r"((a)[1]), "r"((a)[2]), "r"((a)[3]),           \
                   "r"(b0), "r"(b1))

// ---------------------------------------------------------------------------
__global__ void copy_x_kernel(const float* __restrict__ x,
                              const float* __restrict__ rs_f,
                              const float* __restrict__ rs_r,
                              const float* __restrict__ rs_m) {
    if (blockIdx.x == (L * NU) / 256) {
        for (int i = threadIdx.x; i < 3 * NU; i += 256) {
            const float* src = (i < NU) ? rs_f : (i < 2 * NU) ? rs_r : rs_m;
            float v = src[i & (NU - 1)];
            g_sig[i] = 1.0f / (1.0f + expf(-v));
        }
        return;
    }
    int i = blockIdx.x * 256 + threadIdx.x;
    float v = x[i];
    g_y32[0][i] = v;
    g_y16[0][i] = __float2half_rn(v);
}

// All 6 weight transposes in one launch. z: stage = z>>1, which = z&1.
__global__ void transpose_half_all(const float* __restrict__ w1f, const float* __restrict__ w2f,
                                   const float* __restrict__ w1r, const float* __restrict__ w2r,
                                   const float* __restrict__ w1m, const float* __restrict__ w2m) {
    __shared__ float t[32][33];
    int stage = blockIdx.z >> 1;
    int which = blockIdx.z & 1;
    int R = which ? K2 : K1;
    int C = which ? N2 : N1;
    if ((int)blockIdx.x * 32 >= C || (int)blockIdx.y * 32 >= R) return;
    const float* w = which ? (stage == 0 ? w2f : stage == 1 ? w2r : w2m)
                           : (stage == 0 ? w1f : stage == 1 ? w1r : w1m);
    __half* o = which ? g_w2t[stage] : g_w1t[stage];
    int c0 = blockIdx.x * 32, r0 = blockIdx.y * 32;
    for (int j = threadIdx.y; j < 32; j += 8)
        t[j][threadIdx.x] = w[(size_t)(r0 + j) * C + c0 + threadIdx.x];
    __syncthreads();
    for (int j = threadIdx.y; j < 32; j += 8) {
        float v = t[threadIdx.x][j];
        o[(size_t)(c0 + j) * R + r0 + threadIdx.x] = __float2half_rn(v);
    }
}

// ---------------------------------------------------------------------------
__global__ void stats_final_kernel() {     // grid 8, block 256
    int c = blockIdx.x * 256 + threadIdx.x;
    float s = 0.f, q = 0.f;
#pragma unroll
    for (int rg = 0; rg < 32; rg++) { s += g_part[rg][2 * c]; q += g_part[rg][2 * c + 1]; }
    float mean = s * (1.0f / M_);
    float var = q * (1.0f / M_) - mean * mean;
    g_stats[2 * c] = mean;
    g_stats[2 * c + 1] = rsqrtf(var + EPS_F);
}

// LN + leaky-relu, fp16 in -> fp16 out. grid 4096, block 256, 8 halves/thread.
__global__ void prep2_kernel() {
    int i = blockIdx.x * 256 + threadIdx.x;
    uint4 v = ((const uint4*)g_hraw)[i];
    int col = (i * 8) & (N1 - 1);
    __half2* hp = (__half2*)&v;
    uint4 outv;
    __half2* op = (__half2*)&outv;
#pragma unroll
    for (int j = 0; j < 4; j++) {
        float2 xv = __half22float2(hp[j]);
        float4 st = *(const float4*)&g_stats[2 * (col + 2 * j)];
        float a = (xv.x - st.x) * st.y;
        float b = (xv.y - st.z) * st.w;
        a = a > 0.f ? a : 0.2f * a;
        b = b > 0.f ? b : 0.2f * b;
        op[j] = __floats2half2_rn(a, b);
    }
    ((uint4*)g_h2)[i] = outv;
}

// ---------------------------------------------------------------------------
// Stage: A 16K | B 16K. 8 cp.async per thread. (R7 exact)
__device__ __forceinline__ void load_stage(uint32_t sb, int s, int ck,
                                           const __half* A, const __half* B,
                                           int Kt, int m0, int n0) {
    int tid = threadIdx.x;
    int r = tid >> 1;
    int c0 = (tid & 1) * 4;
    uint32_t base = sb + s * STAGE;
    size_t rs = (size_t)Kt * 2;
    size_t kb = (size_t)ck * 128;
    const char* pA = (const char*)A + (size_t)(m0 + r) * rs + kb;
    const char* pB = (const char*)B + (size_t)(n0 + r) * rs + kb;
#pragma unroll
    for (int c = 0; c < 4; c++) {
        int ch = c0 + c;
        uint32_t so = sw128((uint32_t)(r * 128 + ch * 16));
        CP16(base + so,         pA + ch * 16);
        CP16(base + 16384 + so, pB + ch * 16);
    }
    CP_COMMIT();
}

__device__ __forceinline__ void compute_chunk(uint32_t base, int lane, int wm, int wn,
                                              float acc[2][8][4]) {
#pragma unroll
    for (int k16 = 0; k16 < 4; k16++) {
        uint32_t koff = k16 * 32 + (lane >> 4) * 16;
        uint32_t ah[2][4];
#pragma unroll
        for (int mt = 0; mt < 2; mt++) {
            int row = wm * 32 + mt * 16 + (lane & 15);
            uint32_t off = sw128((uint32_t)(row * 128) + koff);
            LDSM4(ah[mt][0], ah[mt][1], ah[mt][2], ah[mt][3], base + off);
        }
        uint32_t bh[8][2];
#pragma unroll
        for (int g = 0; g < 4; g++) {
            int row = wn * 64 + g * 16 + (lane & 15);
            uint32_t off = sw128((uint32_t)(row * 128) + koff);
            uint32_t q0, q1, q2, q3;
            LDSM4(q0, q1, q2, q3, base + 16384 + off);
            bh[2 * g][0] = q0; bh[2 * g][1] = q2;
            bh[2 * g + 1][0] = q1; bh[2 * g + 1][1] = q3;
        }
#pragma unroll
        for (int mt = 0; mt < 2; mt++)
#pragma unroll
            for (int nt = 0; nt < 8; nt++)
                MMA(acc[mt][nt], ah[mt], bh[nt][0], bh[nt][1]);
    }
}

// R7-proven 2-stage double buffer.
__device__ __forceinline__ void gemm_main(uint32_t sb,
                                          const __half* A, const __half* B,
                                          int Kt, int m0, int n0, float acc[2][8][4]) {
#pragma unroll
    for (int i = 0; i < 2; i++)
#pragma unroll
        for (int j = 0; j < 8; j++)
#pragma unroll
            for (int q = 0; q < 4; q++) acc[i][j][q] = 0.f;

    const int NK = Kt >> 6;
    const int lane = threadIdx.x & 31, wid = threadIdx.x >> 5;
    const int wm = wid & 3, wn = wid >> 2;

    load_stage(sb, 0, 0, A, B, Kt, m0, n0);
    for (int ck = 0; ck < NK; ck++) {
        if (ck + 1 < NK) {
            load_stage(sb, (ck + 1) & 1, ck + 1, A, B, Kt, m0, n0);
            asm volatile("cp.async.wait_group 1;" ::: "memory");
        } else {
            asm volatile("cp.async.wait_group 0;" ::: "memory");
        }
        __syncthreads();
        compute_chunk(sb + (ck & 1) * STAGE, lane, wm, wn, acc);
        __syncthreads();
    }
}

// ---------------------------------------------------------------------------
// GEMM1: h(fp16 raw) = y16 @ w1t^T + fused per-CTA column stats partials.
__global__ __launch_bounds__(256, 2) void gemm1_mma(int cur, int stage) {
    extern __shared__ char smem[];
    uint32_t sb = smem_u32(smem);
    int m0 = blockIdx.y * 128, n0 = blockIdx.x * 128;
    float acc[2][8][4];
    gemm_main(sb, g_y16[cur], g_w1t[stage], K1, m0, n0, acc);

    int lane = threadIdx.x & 31, wid = threadIdx.x >> 5;
    int wm = wid & 3, wn = wid >> 2;
#pragma unroll
    for (int mt = 0; mt < 2; mt++) {
        int r0 = m0 + wm * 32 + mt * 16 + (lane >> 2);
#pragma unroll
        for (int nt = 0; nt < 8; nt++) {
            int cc = n0 + wn * 64 + nt * 8 + (lane & 3) * 2;
            *(__half2*)&g_hraw[(size_t)r0 * N1 + cc] =
                __floats2half2_rn(acc[mt][nt][0], acc[mt][nt][1]);
            *(__half2*)&g_hraw[(size_t)(r0 + 8) * N1 + cc] =
                __floats2half2_rn(acc[mt][nt][2], acc[mt][nt][3]);
        }
    }

    // fused column stats over this CTA's 128 rows (exact fp32 acc)
    float s[8][2], q[8][2];
#pragma unroll
    for (int nt = 0; nt < 8; nt++)
#pragma unroll
        for (int p = 0; p < 2; p++) {
            float a0 = acc[0][nt][p], a1 = acc[0][nt][2 + p];
            float a2 = acc[1][nt][p], a3 = acc[1][nt][2 + p];
            s[nt][p] = a0 + a1 + a2 + a3;
            q[nt][p] = a0 * a0 + a1 * a1 + a2 * a2 + a3 * a3;
        }
#pragma unroll
    for (int off = 4; off < 32; off <<= 1)
#pragma unroll
        for (int nt = 0; nt < 8; nt++)
#pragma unroll
            for (int p = 0; p < 2; p++) {
                s[nt][p] += __shfl_xor_sync(0xffffffffu, s[nt][p], off);
                q[nt][p] += __shfl_xor_sync(0xffffffffu, q[nt][p], off);
            }
    float* red = (float*)smem;             // 4KB scratch (post-gemm smem reuse)
    if (lane < 4) {
#pragma unroll
        for (int nt = 0; nt < 8; nt++)
#pragma unroll
            for (int p = 0; p < 2; p++) {
                int cl = wn * 64 + nt * 8 + lane * 2 + p;
                red[(wm * 128 + cl) * 2 + 0] = s[nt][p];
                red[(wm * 128 + cl) * 2 + 1] = q[nt][p];
            }
    }
    __syncthreads();
    if (threadIdx.x < 128) {
        int cl = threadIdx.x;
        float S = red[cl * 2]           + red[(128 + cl) * 2] +
                  red[(256 + cl) * 2]   + red[(384 + cl) * 2];
        float Q = red[cl * 2 + 1]         + red[(128 + cl) * 2 + 1] +
                  red[(256 + cl) * 2 + 1] + red[(384 + cl) * 2 + 1];
        g_part[blockIdx.y][2 * (n0 + cl)]     = S;
        g_part[blockIdx.y][2 * (n0 + cl) + 1] = Q;
    }
}

// ---------------------------------------------------------------------------
// GEMM2: cand = h2 @ w2t^T; epilogue: +b2, fp32 residual, Benes scatter.
__global__ __launch_bounds__(256, 2) void gemm2_mma(int stage, int dir, int cur,
                                                    const float* __restrict__ b2,
                                                    float* __restrict__ dext) {
    extern __shared__ char smem[];
    uint32_t sb = smem_u32(smem);
    int m0 = blockIdx.y * 128, n0 = blockIdx.x * 128;
    float acc[2][8][4];
    gemm_main(sb, g_h2, g_w2t[stage], K2, m0, n0, acc);

    int lane = threadIdx.x & 31, wid = threadIdx.x >> 5;
    int wm = wid & 3, wn = wid >> 2;
    const float* y = g_y32[cur];
    float* oy = g_y32[cur ^ 1];
    __half* o16 = g_y16[cur ^ 1];

#pragma unroll
    for (int mt = 0; mt < 2; mt++) {
        int rbase = m0 + wm * 32 + mt * 16 + (lane >> 2);
#pragma unroll
        for (int nt = 0; nt < 8; nt++) {
            int n = n0 + wn * 64 + nt * 8 + (lane & 3) * 2;
            int c = n & (NU - 1);
            int b = n >> 9;
            float2 bias = *(const float2*)&b2[n];
            float sig0 = g_sig[stage * NU + c];
            float sig1 = g_sig[stage * NU + c + 1];
#pragma unroll
            for (int hf = 0; hf < 2; hf++) {
                int r = rbase + hf * 8;
                int rowY = 2 * r + b;
                float cand0 = acc[mt][nt][hf * 2 + 0] + bias.x;
                float cand1 = acc[mt][nt][hf * 2 + 1] + bias.y;
                float2 yv = *(const float2*)&y[(size_t)rowY * NU + c];
                float v0 = sig0 * yv.x + cand0 * CW_F;
                float v1 = sig1 * yv.y + cand1 * CW_F;
                int dst;
                if (dir == 0)      dst = (rowY < M_) ? (2 * rowY) : (2 * rowY - L + 1);
                else if (dir == 1) dst = (rowY & 1) ? (M_ + (rowY >> 1)) : (rowY >> 1);
                else               dst = rowY;
                if (dext) {
                    *(float2*)&dext[(size_t)dst * NU + c] = make_float2(v0, v1);
                } else {
                    *(float2*)&oy[(size_t)dst * NU + c] = make_float2(v0, v1);
                    *(__half2*)&o16[(size_t)dst * NU + c] =
                        __halves2half2(__float2half_rn(v0), __float2half_rn(v1));
                }
            }
        }
    }
}

// ---------------------------------------------------------------------------
extern "C" void kernel_launch(void* const* d_in, const int* in_sizes, int n_in,
                              void* d_out, int out_size) {
    const float* x = (const float*)d_in[0];
    const float* rs[3] = {(const float*)d_in[1], (const float*)d_in[5], (const float*)d_in[9]};
    const float* w1[3] = {(const float*)d_in[2], (const float*)d_in[6], (const float*)d_in[10]};
    const float* w2[3] = {(const float*)d_in[3], (const float*)d_in[7], (const float*)d_in[11]};
    const float* b2[3] = {(const float*)d_in[4], (const float*)d_in[8], (const float*)d_in[12]};
    float* out = (float*)d_out;

    cudaFuncSetAttribute(gemm1_mma, cudaFuncAttributeMaxDynamicSharedMemorySize, SMEM_DYN);
    cudaFuncSetAttribute(gemm2_mma, cudaFuncAttributeMaxDynamicSharedMemorySize, SMEM_DYN);

    copy_x_kernel<<<(L * NU) / 256 + 1, 256>>>(x, rs[0], rs[1], rs[2]);
    transpose_half_all<<<dim3(64, 64, 6), dim3(32, 8)>>>(w1[0], w2[0], w1[1], w2[1], w1[2], w2[2]);

    dim3 g1(N1 / 128, M_ / 128);   // (16, 32)
    dim3 g2(N2 / 128, M_ / 128);   // (8, 32)

    int cur = 0;
    for (int step = 0; step < 25; step++) {
        int stage = (step < 12) ? 0 : (step < 24) ? 1 : 2;
        int dir = stage;
        gemm1_mma<<<g1, 256, SMEM_DYN>>>(cur, stage);
        stats_final_kernel<<<8, 256>>>();
        prep2_kernel<<<4096, 256>>>();
        gemm2_mma<<<g2, 256, SMEM_DYN>>>(stage, dir, cur, b2[stage],
                                         (step == 24) ? out : nullptr);
        cur ^= 1;
    }
}

// round 17
// speedup vs baseline: 1.4210x; 1.0213x over previous
#include <cuda_runtime.h>
#include <cuda_fp16.h>
#include <cstdint>

// ---------------------------------------------------------------------------
// BenesBlock via mma.sync (HMMA), single-pass fp16 GEMMs.
// R16 = R15 (champion GEMM core, fp16 h) with stats_final FUSED into a
// column-strip prep2 (each block reduces partials for its own 64 columns,
// then LN+lrelu's its strip) -> 3 launches per step.
// ---------------------------------------------------------------------------

#define L    8192
#define NU   512
#define M_   4096
#define K1   1024
#define N1   2048
#define K2   2048
#define N2   1024
#define CW_F 0.10897247358851683f
#define EPS_F 1e-6f

#define STAGE 32768                 // A16K | B16K
#define SMEM_DYN (2 * STAGE)        // 64KB double buffered -> 2 CTAs/SM

// ---------------------------------------------------------------------------
__device__ __align__(16) float  g_y32[2][L * NU];         // exact residual
__device__ __align__(16) __half g_y16[2][L * NU];         // GEMM1 A operand
__device__ __align__(16) __half g_hraw[M_ * N1];          // raw h (fp16)
__device__ __align__(16) __half g_h2[M_ * N1];            // LN'd h (fp16)
__device__ __align__(16) __half g_w1t[3][N1 * K1];        // [stage][N,K] fp16
__device__ __align__(16) __half g_w2t[3][N2 * K2];
__device__ __align__(16) float g_part[32][2 * N1];
__device__ float g_sig[3 * NU];

// ---------------------------------------------------------------------------
__device__ __forceinline__ uint32_t smem_u32(const void* p) {
    uint32_t a;
    asm("{ .reg .u64 t; cvta.to.shared.u64 t, %1; cvt.u32.u64 %0, t; }" : "=r"(a) : "l"(p));
    return a;
}
__device__ __forceinline__ uint32_t sw128(uint32_t off) { return off ^ ((off >> 3) & 0x70); }

#define CP16(s, g) asm volatile("cp.async.cg.shared.global [%0], [%1], 16;" :: "r"(s), "l"(g))
#define CP_COMMIT() asm volatile("cp.async.commit_group;" ::: "memory")

#define LDSM4(r0, r1, r2, r3, addr)                                              \
    asm volatile("ldmatrix.sync.aligned.m8n8.x4.shared.b16 {%0,%1,%2,%3}, [%4];" \
                 : "=r"(r0), "=r"(r1), "=r"(r2), "=r"(r3) : "r"(addr))

#define MMA(acc, a, b0, b1)                                                      \
    asm volatile("mma.sync.aligned.m16n8k16.row.col.f32.f16.f16.f32 "            \
                 "{%0,%1,%2,%3}, {%4,%5,%6,%7}, {%8,%9}, {%0,%1,%2,%3};"         \
                 : "+f"((acc)[0]), "+f"((acc)[1]), "+f"((acc)[2]), "+f"((acc)[3])\
                 : "r"((a)[0]), "r"((a)[1]), "r"((a)[2]), "r"((a)[3]),           \
                   "r"(b0), "r"(b1))

// ---------------------------------------------------------------------------
__global__ void copy_x_kernel(const float* __restrict__ x,
                              const float* __restrict__ rs_f,
                              const float* __restrict__ rs_r,
                              const float* __restrict__ rs_m) {
    if (blockIdx.x == (L * NU) / 256) {
        for (int i = threadIdx.x; i < 3 * NU; i += 256) {
            const float* src = (i < NU) ? rs_f : (i < 2 * NU) ? rs_r : rs_m;
            float v = src[i & (NU - 1)];
            g_sig[i] = 1.0f / (1.0f + expf(-v));
        }
        return;
    }
    int i = blockIdx.x * 256 + threadIdx.x;
    float v = x[i];
    g_y32[0][i] = v;
    g_y16[0][i] = __float2half_rn(v);
}

// All 6 weight transposes in one launch. z: stage = z>>1, which = z&1.
__global__ void transpose_half_all(const float* __restrict__ w1f, const float* __restrict__ w2f,
                                   const float* __restrict__ w1r, const float* __restrict__ w2r,
                                   const float* __restrict__ w1m, const float* __restrict__ w2m) {
    __shared__ float t[32][33];
    int stage = blockIdx.z >> 1;
    int which = blockIdx.z & 1;
    int R = which ? K2 : K1;
    int C = which ? N2 : N1;
    if ((int)blockIdx.x * 32 >= C || (int)blockIdx.y * 32 >= R) return;
    const float* w = which ? (stage == 0 ? w2f : stage == 1 ? w2r : w2m)
                           : (stage == 0 ? w1f : stage == 1 ? w1r : w1m);
    __half* o = which ? g_w2t[stage] : g_w1t[stage];
    int c0 = blockIdx.x * 32, r0 = blockIdx.y * 32;
    for (int j = threadIdx.y; j < 32; j += 8)
        t[j][threadIdx.x] = w[(size_t)(r0 + j) * C + c0 + threadIdx.x];
    __syncthreads();
    for (int j = threadIdx.y; j < 32; j += 8) {
        float v = t[threadIdx.x][j];
        o[(size_t)(c0 + j) * R + r0 + threadIdx.x] = __float2half_rn(v);
    }
}

// ---------------------------------------------------------------------------
// Fused stats + LN + leaky-relu, column-strip layout.
// grid (32, 8), block 256: block owns 64 columns x 512 rows.
// Stats for its 64 columns reduced from g_part in-block (no separate kernel).
__global__ void prep2_kernel() {
    __shared__ float s_mean[64], s_rstd[64];
    int c0 = blockIdx.x * 64;
    if (threadIdx.x < 64) {
        int c = c0 + threadIdx.x;
        float s = 0.f, q = 0.f;
#pragma unroll
        for (int rg = 0; rg < 32; rg++) {
            s += g_part[rg][2 * c];
            q += g_part[rg][2 * c + 1];
        }
        float mean = s * (1.0f / M_);
        float var = q * (1.0f / M_) - mean * mean;
        s_mean[threadIdx.x] = mean;
        s_rstd[threadIdx.x] = rsqrtf(var + EPS_F);
    }
    __syncthreads();

    int seg = threadIdx.x & 7;           // 16B segment within 128B strip row
    int rowoff = threadIdx.x >> 3;       // 0..31
    int cb = seg * 8;                    // column offset within strip
    float mm[8], rr[8];
#pragma unroll
    for (int j = 0; j < 8; j++) { mm[j] = s_mean[cb + j]; rr[j] = s_rstd[cb + j]; }

    int r0 = blockIdx.y * 512;
#pragma unroll 4
    for (int it = 0; it < 16; it++) {
        int r = r0 + it * 32 + rowoff;
        size_t off = ((size_t)r * N1 + c0 + cb) >> 3;    // uint4 units
        uint4 v = ((const uint4*)g_hraw)[off];
        __half2* hp = (__half2*)&v;
        uint4 ov;
        __half2* op = (__half2*)&ov;
#pragma unroll
        for (int j = 0; j < 4; j++) {
            float2 xv = __half22float2(hp[j]);
            float a = (xv.x - mm[2 * j])     * rr[2 * j];
            float b = (xv.y - mm[2 * j + 1]) * rr[2 * j + 1];
            a = a > 0.f ? a : 0.2f * a;
            b = b > 0.f ? b : 0.2f * b;
            op[j] = __floats2half2_rn(a, b);
        }
        ((uint4*)g_h2)[off] = ov;
    }
}

// ---------------------------------------------------------------------------
// Stage: A 16K | B 16K. 8 cp.async per thread. (champion core, unchanged)
__device__ __forceinline__ void load_stage(uint32_t sb, int s, int ck,
                                           const __half* A, const __half* B,
                                           int Kt, int m0, int n0) {
    int tid = threadIdx.x;
    int r = tid >> 1;
    int c0 = (tid & 1) * 4;
    uint32_t base = sb + s * STAGE;
    size_t rs = (size_t)Kt * 2;
    size_t kb = (size_t)ck * 128;
    const char* pA = (const char*)A + (size_t)(m0 + r) * rs + kb;
    const char* pB = (const char*)B + (size_t)(n0 + r) * rs + kb;
#pragma unroll
    for (int c = 0; c < 4; c++) {
        int ch = c0 + c;
        uint32_t so = sw128((uint32_t)(r * 128 + ch * 16));
        CP16(base + so,         pA + ch * 16);
        CP16(base + 16384 + so, pB + ch * 16);
    }
    CP_COMMIT();
}

__device__ __forceinline__ void compute_chunk(uint32_t base, int lane, int wm, int wn,
                                              float acc[2][8][4]) {
#pragma unroll
    for (int k16 = 0; k16 < 4; k16++) {
        uint32_t koff = k16 * 32 + (lane >> 4) * 16;
        uint32_t ah[2][4];
#pragma unroll
        for (int mt = 0; mt < 2; mt++) {
            int row = wm * 32 + mt * 16 + (lane & 15);
            uint32_t off = sw128((uint32_t)(row * 128) + koff);
            LDSM4(ah[mt][0], ah[mt][1], ah[mt][2], ah[mt][3], base + off);
        }
        uint32_t bh[8][2];
#pragma unroll
        for (int g = 0; g < 4; g++) {
            int row = wn * 64 + g * 16 + (lane & 15);
            uint32_t off = sw128((uint32_t)(row * 128) + koff);
            uint32_t q0, q1, q2, q3;
            LDSM4(q0, q1, q2, q3, base + 16384 + off);
            bh[2 * g][0] = q0; bh[2 * g][1] = q2;
            bh[2 * g + 1][0] = q1; bh[2 * g + 1][1] = q3;
        }
#pragma unroll
        for (int mt = 0; mt < 2; mt++)
#pragma unroll
            for (int nt = 0; nt < 8; nt++)
                MMA(acc[mt][nt], ah[mt], bh[nt][0], bh[nt][1]);
    }
}

// 2-stage double buffer (champion core, unchanged).
__device__ __forceinline__ void gemm_main(uint32_t sb,
                                          const __half* A, const __half* B,
                                          int Kt, int m0, int n0, float acc[2][8][4]) {
#pragma unroll
    for (int i = 0; i < 2; i++)
#pragma unroll
        for (int j = 0; j < 8; j++)
#pragma unroll
            for (int q = 0; q < 4; q++) acc[i][j][q] = 0.f;

    const int NK = Kt >> 6;
    const int lane = threadIdx.x & 31, wid = threadIdx.x >> 5;
    const int wm = wid & 3, wn = wid >> 2;

    load_stage(sb, 0, 0, A, B, Kt, m0, n0);
    for (int ck = 0; ck < NK; ck++) {
        if (ck + 1 < NK) {
            load_stage(sb, (ck + 1) & 1, ck + 1, A, B, Kt, m0, n0);
            asm volatile("cp.async.wait_group 1;" ::: "memory");
        } else {
            asm volatile("cp.async.wait_group 0;" ::: "memory");
        }
        __syncthreads();
        compute_chunk(sb + (ck & 1) * STAGE, lane, wm, wn, acc);
        __syncthreads();
    }
}

// ---------------------------------------------------------------------------
// GEMM1: h(fp16 raw) = y16 @ w1t^T + fused per-CTA column stats partials.
__global__ __launch_bounds__(256, 2) void gemm1_mma(int cur, int stage) {
    extern __shared__ char smem[];
    uint32_t sb = smem_u32(smem);
    int m0 = blockIdx.y * 128, n0 = blockIdx.x * 128;
    float acc[2][8][4];
    gemm_main(sb, g_y16[cur], g_w1t[stage], K1, m0, n0, acc);

    int lane = threadIdx.x & 31, wid = threadIdx.x >> 5;
    int wm = wid & 3, wn = wid >> 2;
#pragma unroll
    for (int mt = 0; mt < 2; mt++) {
        int r0 = m0 + wm * 32 + mt * 16 + (lane >> 2);
#pragma unroll
        for (int nt = 0; nt < 8; nt++) {
            int cc = n0 + wn * 64 + nt * 8 + (lane & 3) * 2;
            *(__half2*)&g_hraw[(size_t)r0 * N1 + cc] =
                __floats2half2_rn(acc[mt][nt][0], acc[mt][nt][1]);
            *(__half2*)&g_hraw[(size_t)(r0 + 8) * N1 + cc] =
                __floats2half2_rn(acc[mt][nt][2], acc[mt][nt][3]);
        }
    }

    // fused column stats over this CTA's 128 rows (exact fp32 acc)
    float s[8][2], q[8][2];
#pragma unroll
    for (int nt = 0; nt < 8; nt++)
#pragma unroll
        for (int p = 0; p < 2; p++) {
            float a0 = acc[0][nt][p], a1 = acc[0][nt][2 + p];
            float a2 = acc[1][nt][p], a3 = acc[1][nt][2 + p];
            s[nt][p] = a0 + a1 + a2 + a3;
            q[nt][p] = a0 * a0 + a1 * a1 + a2 * a2 + a3 * a3;
        }
#pragma unroll
    for (int off = 4; off < 32; off <<= 1)
#pragma unroll
        for (int nt = 0; nt < 8; nt++)
#pragma unroll
            for (int p = 0; p < 2; p++) {
                s[nt][p] += __shfl_xor_sync(0xffffffffu, s[nt][p], off);
                q[nt][p] += __shfl_xor_sync(0xffffffffu, q[nt][p], off);
            }
    float* red = (float*)smem;             // 4KB scratch (post-gemm smem reuse)
    if (lane < 4) {
#pragma unroll
        for (int nt = 0; nt < 8; nt++)
#pragma unroll
            for (int p = 0; p < 2; p++) {
                int cl = wn * 64 + nt * 8 + lane * 2 + p;
                red[(wm * 128 + cl) * 2 + 0] = s[nt][p];
                red[(wm * 128 + cl) * 2 + 1] = q[nt][p];
            }
    }
    __syncthreads();
    if (threadIdx.x < 128) {
        int cl = threadIdx.x;
        float S = red[cl * 2]           + red[(128 + cl) * 2] +
                  red[(256 + cl) * 2]   + red[(384 + cl) * 2];
        float Q = red[cl * 2 + 1]         + red[(128 + cl) * 2 + 1] +
                  red[(256 + cl) * 2 + 1] + red[(384 + cl) * 2 + 1];
        g_part[blockIdx.y][2 * (n0 + cl)]     = S;
        g_part[blockIdx.y][2 * (n0 + cl) + 1] = Q;
    }
}

// ---------------------------------------------------------------------------
// GEMM2: cand = h2 @ w2t^T; epilogue: +b2, fp32 residual, Benes scatter.
__global__ __launch_bounds__(256, 2) void gemm2_mma(int stage, int dir, int cur,
                                                    const float* __restrict__ b2,
                                                    float* __restrict__ dext) {
    extern __shared__ char smem[];
    uint32_t sb = smem_u32(smem);
    int m0 = blockIdx.y * 128, n0 = blockIdx.x * 128;
    float acc[2][8][4];
    gemm_main(sb, g_h2, g_w2t[stage], K2, m0, n0, acc);

    int lane = threadIdx.x & 31, wid = threadIdx.x >> 5;
    int wm = wid & 3, wn = wid >> 2;
    const float* y = g_y32[cur];
    float* oy = g_y32[cur ^ 1];
    __half* o16 = g_y16[cur ^ 1];

#pragma unroll
    for (int mt = 0; mt < 2; mt++) {
        int rbase = m0 + wm * 32 + mt * 16 + (lane >> 2);
#pragma unroll
        for (int nt = 0; nt < 8; nt++) {
            int n = n0 + wn * 64 + nt * 8 + (lane & 3) * 2;
            int c = n & (NU - 1);
            int b = n >> 9;
            float2 bias = *(const float2*)&b2[n];
            float sig0 = g_sig[stage * NU + c];
            float sig1 = g_sig[stage * NU + c + 1];
#pragma unroll
            for (int hf = 0; hf < 2; hf++) {
                int r = rbase + hf * 8;
                int rowY = 2 * r + b;
                float cand0 = acc[mt][nt][hf * 2 + 0] + bias.x;
                float cand1 = acc[mt][nt][hf * 2 + 1] + bias.y;
                float2 yv = *(const float2*)&y[(size_t)rowY * NU + c];
                float v0 = sig0 * yv.x + cand0 * CW_F;
                float v1 = sig1 * yv.y + cand1 * CW_F;
                int dst;
                if (dir == 0)      dst = (rowY < M_) ? (2 * rowY) : (2 * rowY - L + 1);
                else if (dir == 1) dst = (rowY & 1) ? (M_ + (rowY >> 1)) : (rowY >> 1);
                else               dst = rowY;
                if (dext) {
                    *(float2*)&dext[(size_t)dst * NU + c] = make_float2(v0, v1);
                } else {
                    *(float2*)&oy[(size_t)dst * NU + c] = make_float2(v0, v1);
                    *(__half2*)&o16[(size_t)dst * NU + c] =
                        __halves2half2(__float2half_rn(v0), __float2half_rn(v1));
                }
            }
        }
    }
}

// ---------------------------------------------------------------------------
extern "C" void kernel_launch(void* const* d_in, const int* in_sizes, int n_in,
                              void* d_out, int out_size) {
    const float* x = (const float*)d_in[0];
    const float* rs[3] = {(const float*)d_in[1], (const float*)d_in[5], (const float*)d_in[9]};
    const float* w1[3] = {(const float*)d_in[2], (const float*)d_in[6], (const float*)d_in[10]};
    const float* w2[3] = {(const float*)d_in[3], (const float*)d_in[7], (const float*)d_in[11]};
    const float* b2[3] = {(const float*)d_in[4], (const float*)d_in[8], (const float*)d_in[12]};
    float* out = (float*)d_out;

    cudaFuncSetAttribute(gemm1_mma, cudaFuncAttributeMaxDynamicSharedMemorySize, SMEM_DYN);
    cudaFuncSetAttribute(gemm2_mma, cudaFuncAttributeMaxDynamicSharedMemorySize, SMEM_DYN);

    copy_x_kernel<<<(L * NU) / 256 + 1, 256>>>(x, rs[0], rs[1], rs[2]);
    transpose_half_all<<<dim3(64, 64, 6), dim3(32, 8)>>>(w1[0], w2[0], w1[1], w2[1], w1[2], w2[2]);

    dim3 g1(N1 / 128, M_ / 128);   // (16, 32)
    dim3 g2(N2 / 128, M_ / 128);   // (8, 32)

    int cur = 0;
    for (int step = 0; step < 25; step++) {
        int stage = (step < 12) ? 0 : (step < 24) ? 1 : 2;
        int dir = stage;
        gemm1_mma<<<g1, 256, SMEM_DYN>>>(cur, stage);
        prep2_kernel<<<dim3(32, 8), 256>>>();
        gemm2_mma<<<g2, 256, SMEM_DYN>>>(stage, dir, cur, b2[stage],
                                         (step == 24) ? out : nullptr);
        cur ^= 1;
    }
}